// round 11
// baseline (speedup 1.0000x reference)
#include <cuda_runtime.h>
#include <math.h>
#include <stdint.h>

// ----- problem constants -----
#define BB 64      // batch
#define TE 128     // encoder timesteps
#define TD 64      // decoder timesteps
#define DE 512     // embedding dim
#define DH 1024    // hidden dim (enc & dec)
#define H3 3072    // 3 * DH
#define VV 32000   // vocab
#define DIN (DE + DH) // decoder input dim = 1536

// ----- scratch (static device globals; no allocation allowed) -----
__device__ float g_xe[(size_t)TE * BB * DE];
__device__ float g_gi_enc[(size_t)TE * BB * H3];
__device__ float g_wdec[(size_t)TD * BB * DE];
__device__ float g_gi_dec[(size_t)TD * BB * H3];
__device__ float g_gi_ctx[(size_t)BB * H3];
__device__ float g_hA[BB * DH];
__device__ float g_hB[BB * DH];
__device__ float g_states[(size_t)BB * TD * DH];  // (B, T_dec, DH) row-major

// ===================== small PTX helpers =====================

__device__ __forceinline__ void cp16(void* s, const void* g) {
    uint32_t sa = (uint32_t)__cvta_generic_to_shared(s);
    asm volatile("cp.async.cg.shared.global [%0], [%1], 16;\n" :: "r"(sa), "l"(g));
}
__device__ __forceinline__ void cp_commit() {
    asm volatile("cp.async.commit_group;\n");
}
template<int N> __device__ __forceinline__ void cp_wait() {
    asm volatile("cp.async.wait_group %0;\n" :: "n"(N));
}
__device__ __forceinline__ uint32_t f2tf(float x) {
    uint32_t r; asm("cvt.rna.tf32.f32 %0, %1;" : "=r"(r) : "f"(x)); return r;
}
// exact 2-term tf32 split: x == as_float(hi) + as_float(lo) + O(2^-22 |x|)
__device__ __forceinline__ void split_tf(float x, uint32_t& hi, uint32_t& lo) {
    hi = f2tf(x);
    float r = x - __uint_as_float(hi);   // exact (Sterbenz-style cancellation)
    lo = f2tf(r);
}
__device__ __forceinline__ void mma_tf32(float* d, const uint32_t* a, const uint32_t* b) {
    asm volatile(
        "mma.sync.aligned.m16n8k8.row.col.f32.tf32.tf32.f32 "
        "{%0,%1,%2,%3}, {%4,%5,%6,%7}, {%8,%9}, {%0,%1,%2,%3};\n"
        : "+f"(d[0]), "+f"(d[1]), "+f"(d[2]), "+f"(d[3])
        : "r"(a[0]), "r"(a[1]), "r"(a[2]), "r"(a[3]), "r"(b[0]), "r"(b[1]));
}

// ===================== gather kernels =====================

__global__ void gather_enc(const int* __restrict__ x, const float* __restrict__ emb,
                           float* __restrict__ out)
{
    int r = blockIdx.x;
    int t = r >> 6;
    int b = r & 63;
    int tok = x[b * TE + t];
    const float4* s = (const float4*)(emb + (size_t)tok * DE);
    float4* d = (float4*)(out + (size_t)r * DE);
    d[threadIdx.x] = s[threadIdx.x];
}

__global__ void gather_dec(const int* __restrict__ labels, const int* __restrict__ bos,
                           const float* __restrict__ emb, float* __restrict__ out)
{
    int r = blockIdx.x;
    int t = r >> 6;
    int b = r & 63;
    int tok = (t == 0) ? bos[0] : labels[b * TD + t - 1];
    const float4* s = (const float4*)(emb + (size_t)tok * DE);
    float4* d = (float4*)(out + (size_t)r * DE);
    d[threadIdx.x] = s[threadIdx.x];
}

__global__ void set_h(float* __restrict__ dst, const float* __restrict__ src)
{
    int i = blockIdx.x * 1024 + threadIdx.x;
    dst[i] = src ? src[i & (DH - 1)] : 0.0f;
}

// ===================== fp32 SGEMM-NT (R6 scalar version: gi / ctx GEMMs, exact) ========
// C[M,N] = A[M,K](row, lda) * B[N,K](row, ldb)^T + bias[N]

__global__ __launch_bounds__(256) void sgemm_nt(
    const float* __restrict__ A, const float* __restrict__ Bm,
    const float* __restrict__ bias, float* __restrict__ C,
    int M, int N, int K, int lda, int ldb)
{
    __shared__ float As[16][132];
    __shared__ float Bs[16][132];

    const int t  = threadIdx.x;
    const int tx = t & 15;
    const int ty = t >> 4;
    const int row0 = blockIdx.y * 128;
    const int col0 = blockIdx.x * 128;

    float acc[8][8];
#pragma unroll
    for (int i = 0; i < 8; i++)
#pragma unroll
        for (int j = 0; j < 8; j++) acc[i][j] = 0.0f;

    for (int k0 = 0; k0 < K; k0 += 16) {
#pragma unroll
        for (int r = 0; r < 2; r++) {
            int id = t + 256 * r;
            int ar = id >> 2;
            int kq = id & 3;
            float4 v = make_float4(0.f, 0.f, 0.f, 0.f);
            int gr = row0 + ar;
            if (gr < M) v = *(const float4*)(A + (size_t)gr * lda + k0 + kq * 4);
            As[kq * 4 + 0][ar] = v.x;
            As[kq * 4 + 1][ar] = v.y;
            As[kq * 4 + 2][ar] = v.z;
            As[kq * 4 + 3][ar] = v.w;
            float4 wv = *(const float4*)(Bm + (size_t)(col0 + ar) * ldb + k0 + kq * 4);
            Bs[kq * 4 + 0][ar] = wv.x;
            Bs[kq * 4 + 1][ar] = wv.y;
            Bs[kq * 4 + 2][ar] = wv.z;
            Bs[kq * 4 + 3][ar] = wv.w;
        }
        __syncthreads();

#pragma unroll
        for (int k = 0; k < 16; k++) {
            float4 a0 = *(const float4*)&As[k][ty * 4];
            float4 a1 = *(const float4*)&As[k][ty * 4 + 64];
            float4 b0 = *(const float4*)&Bs[k][tx * 4];
            float4 b1 = *(const float4*)&Bs[k][tx * 4 + 64];
            float av[8] = {a0.x, a0.y, a0.z, a0.w, a1.x, a1.y, a1.z, a1.w};
            float bv[8] = {b0.x, b0.y, b0.z, b0.w, b1.x, b1.y, b1.z, b1.w};
#pragma unroll
            for (int i = 0; i < 8; i++)
#pragma unroll
                for (int j = 0; j < 8; j++) acc[i][j] += av[i] * bv[j];
        }
        __syncthreads();
    }

    float bc[8];
#pragma unroll
    for (int j = 0; j < 8; j++) {
        int cj = col0 + ((j < 4) ? (tx * 4 + j) : (64 + tx * 4 + j - 4));
        bc[j] = bias ? bias[cj] : 0.0f;
    }
#pragma unroll
    for (int i = 0; i < 8; i++) {
        int ri = row0 + ((i < 4) ? (ty * 4 + i) : (64 + ty * 4 + i - 4));
        if (ri < M) {
            float4 o0 = make_float4(acc[i][0] + bc[0], acc[i][1] + bc[1],
                                    acc[i][2] + bc[2], acc[i][3] + bc[3]);
            float4 o1 = make_float4(acc[i][4] + bc[4], acc[i][5] + bc[5],
                                    acc[i][6] + bc[6], acc[i][7] + bc[7]);
            *(float4*)(C + (size_t)ri * N + col0 + tx * 4)      = o0;
            *(float4*)(C + (size_t)ri * N + col0 + 64 + tx * 4) = o1;
        }
    }
}

// ===================== tf32 tensor-core GEMM-NT (logits projection) =====================
// C[M,N] = A[M,K] * B[N,K]^T + bias[N].  Requires M%128==0, N%128==0, K%16==0, lda=ldb=K.

__global__ __launch_bounds__(256) void gemm_tf32_nt(
    const float* __restrict__ A, const float* __restrict__ Bm,
    const float* __restrict__ bias, float* __restrict__ C,
    int M, int N, int K)
{
    __shared__ float As[2][128][20];
    __shared__ float Bs[2][128][20];

    const int tid  = threadIdx.x;
    const int lane = tid & 31;
    const int wid  = tid >> 5;
    const int wm   = wid >> 1;
    const int wn   = wid & 1;
    const int row0 = blockIdx.y * 128;
    const int col0 = blockIdx.x * 128;

    const int lr  = tid >> 2;
    const int lkq = tid & 3;

    float d[2][8][4];
#pragma unroll
    for (int mt = 0; mt < 2; mt++)
#pragma unroll
        for (int nt = 0; nt < 8; nt++)
#pragma unroll
            for (int q = 0; q < 4; q++) d[mt][nt][q] = 0.0f;

    const int nk = K / 16;

    auto issue = [&](int kt, int p) {
        int k0 = kt * 16;
#pragma unroll
        for (int r = 0; r < 2; r++) {
            int row = lr + r * 64;
            cp16(&As[p][row][lkq * 4], A  + (size_t)(row0 + row) * K + k0 + lkq * 4);
            cp16(&Bs[p][row][lkq * 4], Bm + (size_t)(col0 + row) * K + k0 + lkq * 4);
        }
    };

    issue(0, 0);
    cp_commit();

    int p = 0;
    for (int kt = 0; kt < nk; kt++) {
        if (kt + 1 < nk) {
            issue(kt + 1, p ^ 1);
            cp_commit();
            cp_wait<1>();
        } else {
            cp_wait<0>();
        }
        __syncthreads();

#pragma unroll
        for (int kk = 0; kk < 2; kk++) {
            int k8 = kk * 8;
            uint32_t af[2][4], bf[8][2];
#pragma unroll
            for (int mt = 0; mt < 2; mt++) {
                int mb = wm * 32 + mt * 16;
                af[mt][0] = f2tf(As[p][mb +     (lane >> 2)][k8 +     (lane & 3)]);
                af[mt][1] = f2tf(As[p][mb + 8 + (lane >> 2)][k8 +     (lane & 3)]);
                af[mt][2] = f2tf(As[p][mb +     (lane >> 2)][k8 + 4 + (lane & 3)]);
                af[mt][3] = f2tf(As[p][mb + 8 + (lane >> 2)][k8 + 4 + (lane & 3)]);
            }
#pragma unroll
            for (int nt = 0; nt < 8; nt++) {
                int nb = wn * 64 + nt * 8;
                bf[nt][0] = f2tf(Bs[p][nb + (lane >> 2)][k8 +     (lane & 3)]);
                bf[nt][1] = f2tf(Bs[p][nb + (lane >> 2)][k8 + 4 + (lane & 3)]);
            }
#pragma unroll
            for (int mt = 0; mt < 2; mt++)
#pragma unroll
                for (int nt = 0; nt < 8; nt++)
                    mma_tf32(d[mt][nt], af[mt], bf[nt]);
        }
        __syncthreads();
        p ^= 1;
    }

#pragma unroll
    for (int mt = 0; mt < 2; mt++) {
        int r0 = row0 + wm * 32 + mt * 16 + (lane >> 2);
#pragma unroll
        for (int nt = 0; nt < 8; nt++) {
            int c = col0 + wn * 64 + nt * 8 + (lane & 3) * 2;
            float b0v = bias ? bias[c] : 0.0f;
            float b1v = bias ? bias[c + 1] : 0.0f;
            float2 o0 = make_float2(d[mt][nt][0] + b0v, d[mt][nt][1] + b1v);
            float2 o1 = make_float2(d[mt][nt][2] + b0v, d[mt][nt][3] + b1v);
            *(float2*)(C + (size_t)r0 * N + c)       = o0;
            *(float2*)(C + (size_t)(r0 + 8) * N + c) = o1;
        }
    }
}

// ===================== GRU step via tensor cores (split tf32 == fp32 accuracy) =========
// gh(64 x 3072) = h(64 x 1024) . Whh^T, then fused gate epilogue.
// grid = 64 CTAs; CTA owns 16 hidden cols j (48 gate rows: local row ln = g*16 + jl
// <-> global Whh row g*1024 + jb + jl). 256 threads = 8 warps:
//   warp w: M-tile mt = w>>1 (16 batch rows), N-half ng = w&1 (3 n8-tiles).
// K streamed in 32-wide chunks, cp.async double-buffered. Each operand is split
// 2-term tf32 in-register; 3 MMAs (hi.hi + lo.hi + hi.lo) give ~fp32 products.
// gh staged in smem, then 3-gate epilogue identical numerics to the scalar version.

#define KC 32

__global__ __launch_bounds__(256) void gru_step_mma(
    const float* __restrict__ gi,    // (B,H3) input preactivations (incl. bih)
    const float* __restrict__ gi2,   // optional second term (decoder ctx), or nullptr
    const float* __restrict__ Whh,   // (H3, DH) row-major
    const float* __restrict__ bhh,   // (H3)
    const float* __restrict__ h_in,  // (B, DH)
    float* __restrict__ h_out,       // (B, DH)
    float* __restrict__ st_out,      // optional: states base + t*DH
    int st_stride)
{
    __shared__ __align__(16) float hs[2][64][KC + 4];   // 18432 B
    __shared__ __align__(16) float wsm[2][48][KC + 4];  // 13824 B
    __shared__ __align__(16) float ghs[64][52];         // 13312 B  (total 45568 B)

    const int tid  = threadIdx.x;
    const int lane = tid & 31;
    const int w    = tid >> 5;
    const int mt   = w >> 1;          // 0..3  -> batch rows mt*16..+15
    const int ng   = w & 1;           // 0..1  -> n8-tiles ng*3..ng*3+2
    const int jb   = blockIdx.x * 16;

    const int fr = lane >> 2;         // fragment row within tile
    const int fc = lane & 3;          // fragment k within half

    float acc[3][4];
#pragma unroll
    for (int t = 0; t < 3; t++)
#pragma unroll
        for (int q = 0; q < 4; q++) acc[t][q] = 0.0f;

    auto issue = [&](int kc, int p) {
        const int k0 = kc * KC;
        // h chunk: 64 rows x 32 cols = 512 float4 -> 2 per thread
#pragma unroll
        for (int r = 0; r < 2; r++) {
            int id  = tid + 256 * r;
            int row = id >> 3;
            int q   = id & 7;
            cp16(&hs[p][row][q * 4], h_in + (size_t)row * DH + k0 + q * 4);
        }
        // W chunk: 48 rows x 32 cols = 384 float4
        {
            int row = tid >> 3;       // 0..31
            int q   = tid & 7;
            int grow = (row >> 4) * DH + jb + (row & 15);
            cp16(&wsm[p][row][q * 4], Whh + (size_t)grow * DH + k0 + q * 4);
        }
        if (tid < 128) {
            int id  = tid + 256;
            int row = id >> 3;        // 32..47
            int q   = id & 7;
            int grow = (row >> 4) * DH + jb + (row & 15);
            cp16(&wsm[p][row][q * 4], Whh + (size_t)grow * DH + k0 + q * 4);
        }
    };

    issue(0, 0);
    cp_commit();

    int p = 0;
    const int nchunk = DH / KC;       // 32
    for (int kc = 0; kc < nchunk; kc++) {
        if (kc + 1 < nchunk) {
            issue(kc + 1, p ^ 1);
            cp_commit();
            cp_wait<1>();
        } else {
            cp_wait<0>();
        }
        __syncthreads();

#pragma unroll
        for (int k8 = 0; k8 < KC / 8; k8++) {
            const int kb = k8 * 8;
            // A fragment (batch x k) + split
            float a0 = hs[p][mt * 16 + fr    ][kb + fc    ];
            float a1 = hs[p][mt * 16 + fr + 8][kb + fc    ];
            float a2 = hs[p][mt * 16 + fr    ][kb + fc + 4];
            float a3 = hs[p][mt * 16 + fr + 8][kb + fc + 4];
            uint32_t ah[4], al[4];
            split_tf(a0, ah[0], al[0]);
            split_tf(a1, ah[1], al[1]);
            split_tf(a2, ah[2], al[2]);
            split_tf(a3, ah[3], al[3]);
#pragma unroll
            for (int t = 0; t < 3; t++) {
                int nb = (ng * 3 + t) * 8;
                float b0 = wsm[p][nb + fr][kb + fc    ];
                float b1 = wsm[p][nb + fr][kb + fc + 4];
                uint32_t bh[2], bl[2];
                split_tf(b0, bh[0], bl[0]);
                split_tf(b1, bh[1], bl[1]);
                mma_tf32(acc[t], ah, bh);
                mma_tf32(acc[t], al, bh);
                mma_tf32(acc[t], ah, bl);
            }
        }
        __syncthreads();
        p ^= 1;
    }

    // stage gh to smem
#pragma unroll
    for (int t = 0; t < 3; t++) {
        int col = (ng * 3 + t) * 8 + fc * 2;
        int r0  = mt * 16 + fr;
        *(float2*)&ghs[r0    ][col] = make_float2(acc[t][0], acc[t][1]);
        *(float2*)&ghs[r0 + 8][col] = make_float2(acc[t][2], acc[t][3]);
    }
    __syncthreads();

    // fused gate epilogue: 1024 (b, jl) outputs, 4 per thread
#pragma unroll
    for (int u = 0; u < 4; u++) {
        int e  = tid + 256 * u;       // 0..1023
        int b  = e >> 4;
        int jl = e & 15;
        int j  = jb + jl;
        float ghr = ghs[b][jl]      + bhh[j];
        float ghz = ghs[b][16 + jl] + bhh[j + DH];
        float ghn = ghs[b][32 + jl] + bhh[j + 2 * DH];
        size_t base = (size_t)b * H3 + j;
        float gir = gi[base];
        float giz = gi[base + DH];
        float gin = gi[base + 2 * DH];
        if (gi2) {
            gir += gi2[base];
            giz += gi2[base + DH];
            gin += gi2[base + 2 * DH];
        }
        float rr = 1.0f / (1.0f + expf(-(gir + ghr)));
        float zz = 1.0f / (1.0f + expf(-(giz + ghz)));
        float nn = tanhf(gin + rr * ghn);
        float hold = h_in[(size_t)b * DH + j];
        float hv = (1.0f - zz) * nn + zz * hold;
        h_out[(size_t)b * DH + j] = hv;
        if (st_out) st_out[(size_t)b * st_stride + j] = hv;
    }
}

// ===================== launcher =====================

extern "C" void kernel_launch(void* const* d_in, const int* in_sizes, int n_in,
                              void* d_out, int out_size)
{
    const int*   x        = (const int*)d_in[0];
    const int*   labels   = (const int*)d_in[1];
    const int*   bos      = (const int*)d_in[2];
    const float* enc_emb  = (const float*)d_in[3];
    const float* enc_Wih  = (const float*)d_in[4];
    const float* enc_Whh  = (const float*)d_in[5];
    const float* enc_bih  = (const float*)d_in[6];
    const float* enc_bhh  = (const float*)d_in[7];
    const float* dec_emb  = (const float*)d_in[8];
    const float* dec_Wih  = (const float*)d_in[9];
    const float* dec_Whh  = (const float*)d_in[10];
    const float* dec_bih  = (const float*)d_in[11];
    const float* dec_bhh  = (const float*)d_in[12];
    const float* dec_init = (const float*)d_in[13];
    const float* lin_W    = (const float*)d_in[14];
    const float* lin_b    = (const float*)d_in[15];
    float* out = (float*)d_out;

    float *xe, *gi_enc, *wdec, *gi_dec, *gi_ctx, *hA, *hB, *states;
    cudaGetSymbolAddress((void**)&xe,     g_xe);
    cudaGetSymbolAddress((void**)&gi_enc, g_gi_enc);
    cudaGetSymbolAddress((void**)&wdec,   g_wdec);
    cudaGetSymbolAddress((void**)&gi_dec, g_gi_dec);
    cudaGetSymbolAddress((void**)&gi_ctx, g_gi_ctx);
    cudaGetSymbolAddress((void**)&hA,     g_hA);
    cudaGetSymbolAddress((void**)&hB,     g_hB);
    cudaGetSymbolAddress((void**)&states, g_states);

    // ---- encoder ----
    gather_enc<<<TE * BB, 128>>>(x, enc_emb, xe);
    sgemm_nt<<<dim3(H3 / 128, (TE * BB) / 128), 256>>>(
        xe, enc_Wih, enc_bih, gi_enc, TE * BB, H3, DE, DE, DE);
    set_h<<<64, 1024>>>(hA, nullptr);
    for (int t = 0; t < TE; t++) {
        float* hin  = (t & 1) ? hB : hA;
        float* hout = (t & 1) ? hA : hB;
        gru_step_mma<<<64, 256>>>(gi_enc + (size_t)t * BB * H3, nullptr,
                                  enc_Whh, enc_bhh, hin, hout, nullptr, 0);
    }
    // encoder final hidden state now in hA (TE even)

    // ---- decoder precompute ----
    gather_dec<<<TD * BB, 128>>>(labels, bos, dec_emb, wdec);
    sgemm_nt<<<dim3(H3 / 128, (TD * BB) / 128), 256>>>(
        wdec, dec_Wih, dec_bih, gi_dec, TD * BB, H3, DE, DE, DIN);
    sgemm_nt<<<dim3(H3 / 128, 1), 256>>>(
        hA, dec_Wih + DE, nullptr, gi_ctx, BB, H3, DH, DH, DIN);
    set_h<<<64, 1024>>>(hA, dec_init);

    // ---- decoder recurrence ----
    for (int t = 0; t < TD; t++) {
        float* hin  = (t & 1) ? hB : hA;
        float* hout = (t & 1) ? hA : hB;
        gru_step_mma<<<64, 256>>>(gi_dec + (size_t)t * BB * H3, gi_ctx,
                                  dec_Whh, dec_bhh, hin, hout,
                                  states + (size_t)t * DH, TD * DH);
    }

    // ---- output projection (tf32 tensor cores): logits = states * lin_W^T + lin_b ----
    gemm_tf32_nt<<<dim3(VV / 128, (TD * BB) / 128), 256>>>(
        states, lin_W, lin_b, out, TD * BB, VV, DH);
}

// round 12
// speedup vs baseline: 2.1443x; 2.1443x over previous
#include <cuda_runtime.h>
#include <cuda_bf16.h>
#include <math.h>
#include <stdint.h>

// ----- problem constants -----
#define BB 64      // batch
#define TE 128     // encoder timesteps
#define TD 64      // decoder timesteps
#define DE 512     // embedding dim
#define DH 1024    // hidden dim (enc & dec)
#define H3 3072    // 3 * DH
#define VV 32000   // vocab
#define DIN (DE + DH) // decoder input dim = 1536
#define KW 512     // packed words per row (DH/2)

// ----- scratch (static device globals; no allocation allowed) -----
__device__ float g_xe[(size_t)TE * BB * DE];
__device__ float g_gi_enc[(size_t)TE * BB * H3];
__device__ float g_wdec[(size_t)TD * BB * DE];
__device__ float g_gi_dec[(size_t)TD * BB * H3];
__device__ float g_gi_ctx[(size_t)BB * H3];
__device__ float g_hA[BB * DH];
__device__ float g_hB[BB * DH];
__device__ float g_states[(size_t)BB * TD * DH];  // (B, T_dec, DH) row-major

// pre-split bf16 weights (hi/lo), packed 2 bf16 per uint32 along k
__device__ uint32_t g_Wh_enc[(size_t)H3 * KW];
__device__ uint32_t g_Wl_enc[(size_t)H3 * KW];
__device__ uint32_t g_Wh_dec[(size_t)H3 * KW];
__device__ uint32_t g_Wl_dec[(size_t)H3 * KW];
// packed hidden state (ping-pong)
__device__ uint32_t g_hp_h[2][BB * KW];
__device__ uint32_t g_hp_l[2][BB * KW];

// ===================== small PTX helpers =====================

__device__ __forceinline__ void cp16(void* s, const void* g) {
    uint32_t sa = (uint32_t)__cvta_generic_to_shared(s);
    asm volatile("cp.async.cg.shared.global [%0], [%1], 16;\n" :: "r"(sa), "l"(g));
}
__device__ __forceinline__ void cp_commit() {
    asm volatile("cp.async.commit_group;\n");
}
template<int N> __device__ __forceinline__ void cp_wait() {
    asm volatile("cp.async.wait_group %0;\n" :: "n"(N));
}
__device__ __forceinline__ uint32_t f2tf(float x) {
    uint32_t r; asm("cvt.rna.tf32.f32 %0, %1;" : "=r"(r) : "f"(x)); return r;
}
__device__ __forceinline__ void mma_tf32(float* d, const uint32_t* a, const uint32_t* b) {
    asm volatile(
        "mma.sync.aligned.m16n8k8.row.col.f32.tf32.tf32.f32 "
        "{%0,%1,%2,%3}, {%4,%5,%6,%7}, {%8,%9}, {%0,%1,%2,%3};\n"
        : "+f"(d[0]), "+f"(d[1]), "+f"(d[2]), "+f"(d[3])
        : "r"(a[0]), "r"(a[1]), "r"(a[2]), "r"(a[3]), "r"(b[0]), "r"(b[1]));
}
__device__ __forceinline__ void mma_bf16(float* d, const uint32_t* a, const uint32_t* b) {
    asm volatile(
        "mma.sync.aligned.m16n8k16.row.col.f32.bf16.bf16.f32 "
        "{%0,%1,%2,%3}, {%4,%5,%6,%7}, {%8,%9}, {%0,%1,%2,%3};\n"
        : "+f"(d[0]), "+f"(d[1]), "+f"(d[2]), "+f"(d[3])
        : "r"(a[0]), "r"(a[1]), "r"(a[2]), "r"(a[3]), "r"(b[0]), "r"(b[1]));
}
// split x into bf16 hi + bf16 lo (residual); pack pairs into uint32 (even k = low half)
__device__ __forceinline__ void split_pack(float x0, float x1,
                                           uint32_t& ph, uint32_t& pl) {
    __nv_bfloat16 h0 = __float2bfloat16_rn(x0);
    __nv_bfloat16 h1 = __float2bfloat16_rn(x1);
    float l0f = x0 - __bfloat162float(h0);
    float l1f = x1 - __bfloat162float(h1);
    __nv_bfloat16 l0 = __float2bfloat16_rn(l0f);
    __nv_bfloat16 l1 = __float2bfloat16_rn(l1f);
    ph = ((uint32_t)__bfloat16_as_ushort(h1) << 16) | (uint32_t)__bfloat16_as_ushort(h0);
    pl = ((uint32_t)__bfloat16_as_ushort(l1) << 16) | (uint32_t)__bfloat16_as_ushort(l0);
}

// ===================== gather / init / pack kernels =====================

__global__ void gather_enc(const int* __restrict__ x, const float* __restrict__ emb,
                           float* __restrict__ out)
{
    int r = blockIdx.x;
    int t = r >> 6;
    int b = r & 63;
    int tok = x[b * TE + t];
    const float4* s = (const float4*)(emb + (size_t)tok * DE);
    float4* d = (float4*)(out + (size_t)r * DE);
    d[threadIdx.x] = s[threadIdx.x];
}

__global__ void gather_dec(const int* __restrict__ labels, const int* __restrict__ bos,
                           const float* __restrict__ emb, float* __restrict__ out)
{
    int r = blockIdx.x;
    int t = r >> 6;
    int b = r & 63;
    int tok = (t == 0) ? bos[0] : labels[b * TD + t - 1];
    const float4* s = (const float4*)(emb + (size_t)tok * DE);
    float4* d = (float4*)(out + (size_t)r * DE);
    d[threadIdx.x] = s[threadIdx.x];
}

// pack one weight matrix (H3 x DH) into bf16 hi/lo packed-pair arrays
__global__ void pack_w(const float* __restrict__ W,
                       uint32_t* __restrict__ Wh, uint32_t* __restrict__ Wl)
{
    int r = blockIdx.x;      // 0..H3-1
    int c = threadIdx.x;     // 0..KW-1
    float x0 = W[(size_t)r * DH + 2 * c];
    float x1 = W[(size_t)r * DH + 2 * c + 1];
    uint32_t ph, pl;
    split_pack(x0, x1, ph, pl);
    Wh[(size_t)r * KW + c] = ph;
    Wl[(size_t)r * KW + c] = pl;
}

// init h (float + packed). src broadcast per-row or zeros.
__global__ void set_h_packed(float* __restrict__ f,
                             uint32_t* __restrict__ ph, uint32_t* __restrict__ pl,
                             const float* __restrict__ src)
{
    int b = blockIdx.x;      // 0..63
    int c = threadIdx.x;     // 0..511
    float x0 = src ? src[2 * c] : 0.0f;
    float x1 = src ? src[2 * c + 1] : 0.0f;
    f[b * DH + 2 * c]     = x0;
    f[b * DH + 2 * c + 1] = x1;
    uint32_t vh, vl;
    split_pack(x0, x1, vh, vl);
    ph[b * KW + c] = vh;
    pl[b * KW + c] = vl;
}

// ===================== fp32 SGEMM-NT (R6 scalar version: gi / ctx GEMMs, exact) ========

__global__ __launch_bounds__(256) void sgemm_nt(
    const float* __restrict__ A, const float* __restrict__ Bm,
    const float* __restrict__ bias, float* __restrict__ C,
    int M, int N, int K, int lda, int ldb)
{
    __shared__ float As[16][132];
    __shared__ float Bs[16][132];

    const int t  = threadIdx.x;
    const int tx = t & 15;
    const int ty = t >> 4;
    const int row0 = blockIdx.y * 128;
    const int col0 = blockIdx.x * 128;

    float acc[8][8];
#pragma unroll
    for (int i = 0; i < 8; i++)
#pragma unroll
        for (int j = 0; j < 8; j++) acc[i][j] = 0.0f;

    for (int k0 = 0; k0 < K; k0 += 16) {
#pragma unroll
        for (int r = 0; r < 2; r++) {
            int id = t + 256 * r;
            int ar = id >> 2;
            int kq = id & 3;
            float4 v = make_float4(0.f, 0.f, 0.f, 0.f);
            int gr = row0 + ar;
            if (gr < M) v = *(const float4*)(A + (size_t)gr * lda + k0 + kq * 4);
            As[kq * 4 + 0][ar] = v.x;
            As[kq * 4 + 1][ar] = v.y;
            As[kq * 4 + 2][ar] = v.z;
            As[kq * 4 + 3][ar] = v.w;
            float4 wv = *(const float4*)(Bm + (size_t)(col0 + ar) * ldb + k0 + kq * 4);
            Bs[kq * 4 + 0][ar] = wv.x;
            Bs[kq * 4 + 1][ar] = wv.y;
            Bs[kq * 4 + 2][ar] = wv.z;
            Bs[kq * 4 + 3][ar] = wv.w;
        }
        __syncthreads();

#pragma unroll
        for (int k = 0; k < 16; k++) {
            float4 a0 = *(const float4*)&As[k][ty * 4];
            float4 a1 = *(const float4*)&As[k][ty * 4 + 64];
            float4 b0 = *(const float4*)&Bs[k][tx * 4];
            float4 b1 = *(const float4*)&Bs[k][tx * 4 + 64];
            float av[8] = {a0.x, a0.y, a0.z, a0.w, a1.x, a1.y, a1.z, a1.w};
            float bv[8] = {b0.x, b0.y, b0.z, b0.w, b1.x, b1.y, b1.z, b1.w};
#pragma unroll
            for (int i = 0; i < 8; i++)
#pragma unroll
                for (int j = 0; j < 8; j++) acc[i][j] += av[i] * bv[j];
        }
        __syncthreads();
    }

    float bc[8];
#pragma unroll
    for (int j = 0; j < 8; j++) {
        int cj = col0 + ((j < 4) ? (tx * 4 + j) : (64 + tx * 4 + j - 4));
        bc[j] = bias ? bias[cj] : 0.0f;
    }
#pragma unroll
    for (int i = 0; i < 8; i++) {
        int ri = row0 + ((i < 4) ? (ty * 4 + i) : (64 + ty * 4 + i - 4));
        if (ri < M) {
            float4 o0 = make_float4(acc[i][0] + bc[0], acc[i][1] + bc[1],
                                    acc[i][2] + bc[2], acc[i][3] + bc[3]);
            float4 o1 = make_float4(acc[i][4] + bc[4], acc[i][5] + bc[5],
                                    acc[i][6] + bc[6], acc[i][7] + bc[7]);
            *(float4*)(C + (size_t)ri * N + col0 + tx * 4)      = o0;
            *(float4*)(C + (size_t)ri * N + col0 + 64 + tx * 4) = o1;
        }
    }
}

// ===================== tf32 tensor-core GEMM-NT (logits projection) =====================

__global__ __launch_bounds__(256) void gemm_tf32_nt(
    const float* __restrict__ A, const float* __restrict__ Bm,
    const float* __restrict__ bias, float* __restrict__ C,
    int M, int N, int K)
{
    __shared__ float As[2][128][20];
    __shared__ float Bs[2][128][20];

    const int tid  = threadIdx.x;
    const int lane = tid & 31;
    const int wid  = tid >> 5;
    const int wm   = wid >> 1;
    const int wn   = wid & 1;
    const int row0 = blockIdx.y * 128;
    const int col0 = blockIdx.x * 128;

    const int lr  = tid >> 2;
    const int lkq = tid & 3;

    float d[2][8][4];
#pragma unroll
    for (int mt = 0; mt < 2; mt++)
#pragma unroll
        for (int nt = 0; nt < 8; nt++)
#pragma unroll
            for (int q = 0; q < 4; q++) d[mt][nt][q] = 0.0f;

    const int nk = K / 16;

    auto issue = [&](int kt, int p) {
        int k0 = kt * 16;
#pragma unroll
        for (int r = 0; r < 2; r++) {
            int row = lr + r * 64;
            cp16(&As[p][row][lkq * 4], A  + (size_t)(row0 + row) * K + k0 + lkq * 4);
            cp16(&Bs[p][row][lkq * 4], Bm + (size_t)(col0 + row) * K + k0 + lkq * 4);
        }
    };

    issue(0, 0);
    cp_commit();

    int p = 0;
    for (int kt = 0; kt < nk; kt++) {
        if (kt + 1 < nk) {
            issue(kt + 1, p ^ 1);
            cp_commit();
            cp_wait<1>();
        } else {
            cp_wait<0>();
        }
        __syncthreads();

#pragma unroll
        for (int kk = 0; kk < 2; kk++) {
            int k8 = kk * 8;
            uint32_t af[2][4], bf[8][2];
#pragma unroll
            for (int mt = 0; mt < 2; mt++) {
                int mb = wm * 32 + mt * 16;
                af[mt][0] = f2tf(As[p][mb +     (lane >> 2)][k8 +     (lane & 3)]);
                af[mt][1] = f2tf(As[p][mb + 8 + (lane >> 2)][k8 +     (lane & 3)]);
                af[mt][2] = f2tf(As[p][mb +     (lane >> 2)][k8 + 4 + (lane & 3)]);
                af[mt][3] = f2tf(As[p][mb + 8 + (lane >> 2)][k8 + 4 + (lane & 3)]);
            }
#pragma unroll
            for (int nt = 0; nt < 8; nt++) {
                int nb = wn * 64 + nt * 8;
                bf[nt][0] = f2tf(Bs[p][nb + (lane >> 2)][k8 +     (lane & 3)]);
                bf[nt][1] = f2tf(Bs[p][nb + (lane >> 2)][k8 + 4 + (lane & 3)]);
            }
#pragma unroll
            for (int mt = 0; mt < 2; mt++)
#pragma unroll
                for (int nt = 0; nt < 8; nt++)
                    mma_tf32(d[mt][nt], af[mt], bf[nt]);
        }
        __syncthreads();
        p ^= 1;
    }

#pragma unroll
    for (int mt = 0; mt < 2; mt++) {
        int r0 = row0 + wm * 32 + mt * 16 + (lane >> 2);
#pragma unroll
        for (int nt = 0; nt < 8; nt++) {
            int c = col0 + wn * 64 + nt * 8 + (lane & 3) * 2;
            float b0v = bias ? bias[c] : 0.0f;
            float b1v = bias ? bias[c + 1] : 0.0f;
            float2 o0 = make_float2(d[mt][nt][0] + b0v, d[mt][nt][1] + b1v);
            float2 o1 = make_float2(d[mt][nt][2] + b0v, d[mt][nt][3] + b1v);
            *(float2*)(C + (size_t)r0 * N + c)       = o0;
            *(float2*)(C + (size_t)(r0 + 8) * N + c) = o1;
        }
    }
}

// ===================== GRU step via bf16-split tensor cores =====================
// gh(64 x 3072) = h(64 x 1024) . Whh^T with PRE-SPLIT bf16 operands:
//   x = x_hi + x_lo (bf16 each, residual split); product via 3 MMAs
//   (hi.hi + lo.hi + hi.lo), dropped lo.lo term ~2^-18 relative. No in-loop
//   conversion ALU; fragments load as packed uint32 pairs, conflict-free.
// grid = 64 CTAs (16 j's = 48 gate rows each); 256 threads = 8 warps:
//   warp w: mt = w>>1 (16 batch rows), ng = w&1 (3 n8 tiles).
// m16n8k16 bf16 MMA; K in 32-float (16-word) double-buffered cp.async stages.
// Epilogue: fused gates + writes next h in float AND packed-split form.

#define GW 20   // padded smem row stride in words (16 data + 4) -> conflict-free

__global__ __launch_bounds__(256) void gru_step_bf16(
    const float* __restrict__ gi,      // (B,H3) input preactivations (incl. bih)
    const float* __restrict__ gi2,     // optional second term, or nullptr
    const uint32_t* __restrict__ Wh,   // (H3, KW) packed bf16-hi pairs
    const uint32_t* __restrict__ Wl,   // (H3, KW) packed bf16-lo pairs
    const float* __restrict__ bhh,     // (H3)
    const float* __restrict__ h_in,    // (B, DH) float state (for z-gate hold)
    const uint32_t* __restrict__ hp_h, // (B, KW) packed state hi
    const uint32_t* __restrict__ hp_l, // (B, KW) packed state lo
    float* __restrict__ h_out,
    uint32_t* __restrict__ hpo_h, uint32_t* __restrict__ hpo_l,
    float* __restrict__ st_out, int st_stride)
{
    // manual smem layout (words):
    //   hs: [arr(2)][stage(2)][64][GW]  at 0      (2*2*64*20 = 5120)
    //   ws: [arr(2)][stage(2)][48][GW]  at 5120   (2*2*48*20 = 3840)
    //   ghs (float [64][52]) reuses offset 0 after mainloop
    __shared__ __align__(16) uint32_t buf[8960];
#define HSW(arr,p,row,w) buf[(arr)*2560 + (p)*1280 + (row)*GW + (w)]
#define WSW(arr,p,row,w) buf[5120 + (arr)*1920 + (p)*960 + (row)*GW + (w)]

    const int tid  = threadIdx.x;
    const int lane = tid & 31;
    const int w    = tid >> 5;
    const int mt   = w >> 1;            // 0..3 -> batch rows mt*16..+15
    const int ng   = w & 1;             // 0..1 -> n8 tiles ng*3..+2
    const int jb   = blockIdx.x * 16;
    const int g    = lane >> 2;         // 0..7
    const int t4   = lane & 3;          // 0..3

    float acc[3][4];
#pragma unroll
    for (int tt = 0; tt < 3; tt++)
#pragma unroll
        for (int q = 0; q < 4; q++) acc[tt][q] = 0.0f;

    auto issue = [&](int kc, int p) {
        const int kb = kc * 16;  // word offset into KW=512 packed row
        // hs: 2 arrays x 64 rows x 4 cp16 = 512
#pragma unroll
        for (int r = 0; r < 2; r++) {
            int id  = tid + 256 * r;
            int arr = id >> 8;
            int rem = id & 255;
            int row = rem >> 2;
            int q   = rem & 3;
            const uint32_t* src = (arr ? hp_l : hp_h) + row * KW + kb + q * 4;
            cp16(&HSW(arr, p, row, q * 4), src);
        }
        // ws: 2 arrays x 48 rows x 4 cp16 = 384
        {
            int id  = tid;
            int arr = (id >= 192) ? 1 : 0;
            int rem = id - arr * 192;
            int row = rem >> 2;
            int q   = rem & 3;
            int grow = (row >> 4) * DH + jb + (row & 15);
            const uint32_t* src = (arr ? Wl : Wh) + (size_t)grow * KW + kb + q * 4;
            cp16(&WSW(arr, p, row, q * 4), src);
        }
        if (tid < 128) {
            int rem = tid + 64;            // rows 16..47 of lo array
            int row = rem >> 2;
            int q   = rem & 3;
            int grow = (row >> 4) * DH + jb + (row & 15);
            cp16(&WSW(1, p, row, q * 4), Wl + (size_t)grow * KW + kb + q * 4);
        }
    };

    issue(0, 0);
    cp_commit();

    int p = 0;
    const int nchunk = DH / 32;    // 32 stages (32 floats = 16 words each)
    for (int kc = 0; kc < nchunk; kc++) {
        if (kc + 1 < nchunk) {
            issue(kc + 1, p ^ 1);
            cp_commit();
            cp_wait<1>();
        } else {
            cp_wait<0>();
        }
        __syncthreads();

#pragma unroll
        for (int c = 0; c < 2; c++) {          // two k16 chunks per stage
            const int wb = c * 8;
            uint32_t ah[4], al[4];
            ah[0] = HSW(0, p, mt * 16 + g,     wb + t4);
            ah[1] = HSW(0, p, mt * 16 + g + 8, wb + t4);
            ah[2] = HSW(0, p, mt * 16 + g,     wb + t4 + 4);
            ah[3] = HSW(0, p, mt * 16 + g + 8, wb + t4 + 4);
            al[0] = HSW(1, p, mt * 16 + g,     wb + t4);
            al[1] = HSW(1, p, mt * 16 + g + 8, wb + t4);
            al[2] = HSW(1, p, mt * 16 + g,     wb + t4 + 4);
            al[3] = HSW(1, p, mt * 16 + g + 8, wb + t4 + 4);
#pragma unroll
            for (int tt = 0; tt < 3; tt++) {
                int n0 = (ng * 3 + tt) * 8;
                uint32_t bh[2], bl[2];
                bh[0] = WSW(0, p, n0 + g, wb + t4);
                bh[1] = WSW(0, p, n0 + g, wb + t4 + 4);
                bl[0] = WSW(1, p, n0 + g, wb + t4);
                bl[1] = WSW(1, p, n0 + g, wb + t4 + 4);
                mma_bf16(acc[tt], ah, bh);
                mma_bf16(acc[tt], al, bh);
                mma_bf16(acc[tt], ah, bl);
            }
        }
        __syncthreads();
        p ^= 1;
    }

    // stage gh to smem (reuse buf; all warps are past the loop's final barrier)
    float* ghs = (float*)buf;   // [64][52]
#pragma unroll
    for (int tt = 0; tt < 3; tt++) {
        int col = (ng * 3 + tt) * 8 + t4 * 2;
        int r0  = mt * 16 + g;
        *(float2*)&ghs[r0 * 52 + col]       = make_float2(acc[tt][0], acc[tt][1]);
        *(float2*)&ghs[(r0 + 8) * 52 + col] = make_float2(acc[tt][2], acc[tt][3]);
    }
    __syncthreads();

    // fused gate epilogue: 512 (b, j-pair) items, 2 per thread
#pragma unroll
    for (int u = 0; u < 2; u++) {
        int e  = tid + 256 * u;     // 0..511
        int b  = e >> 3;
        int jp = e & 7;
        float hv[2];
#pragma unroll
        for (int s = 0; s < 2; s++) {
            int jl = jp * 2 + s;
            int j  = jb + jl;
            float ghr = ghs[b * 52 + jl]      + bhh[j];
            float ghz = ghs[b * 52 + 16 + jl] + bhh[j + DH];
            float ghn = ghs[b * 52 + 32 + jl] + bhh[j + 2 * DH];
            size_t base = (size_t)b * H3 + j;
            float gir = gi[base];
            float giz = gi[base + DH];
            float gin = gi[base + 2 * DH];
            if (gi2) {
                gir += gi2[base];
                giz += gi2[base + DH];
                gin += gi2[base + 2 * DH];
            }
            float rr = 1.0f / (1.0f + expf(-(gir + ghr)));
            float zz = 1.0f / (1.0f + expf(-(giz + ghz)));
            float nn = tanhf(gin + rr * ghn);
            float hold = h_in[(size_t)b * DH + j];
            hv[s] = (1.0f - zz) * nn + zz * hold;
            h_out[(size_t)b * DH + j] = hv[s];
            if (st_out) st_out[(size_t)b * st_stride + j] = hv[s];
        }
        uint32_t ph, pl;
        split_pack(hv[0], hv[1], ph, pl);
        int pidx = b * KW + (jb >> 1) + jp;
        hpo_h[pidx] = ph;
        hpo_l[pidx] = pl;
    }
#undef HSW
#undef WSW
}

// ===================== launcher =====================

extern "C" void kernel_launch(void* const* d_in, const int* in_sizes, int n_in,
                              void* d_out, int out_size)
{
    const int*   x        = (const int*)d_in[0];
    const int*   labels   = (const int*)d_in[1];
    const int*   bos      = (const int*)d_in[2];
    const float* enc_emb  = (const float*)d_in[3];
    const float* enc_Wih  = (const float*)d_in[4];
    const float* enc_Whh  = (const float*)d_in[5];
    const float* enc_bih  = (const float*)d_in[6];
    const float* enc_bhh  = (const float*)d_in[7];
    const float* dec_emb  = (const float*)d_in[8];
    const float* dec_Wih  = (const float*)d_in[9];
    const float* dec_Whh  = (const float*)d_in[10];
    const float* dec_bih  = (const float*)d_in[11];
    const float* dec_bhh  = (const float*)d_in[12];
    const float* dec_init = (const float*)d_in[13];
    const float* lin_W    = (const float*)d_in[14];
    const float* lin_b    = (const float*)d_in[15];
    float* out = (float*)d_out;

    float *xe, *gi_enc, *wdec, *gi_dec, *gi_ctx, *hA, *hB, *states;
    uint32_t *WhE, *WlE, *WhD, *WlD, *hpH, *hpL;
    cudaGetSymbolAddress((void**)&xe,     g_xe);
    cudaGetSymbolAddress((void**)&gi_enc, g_gi_enc);
    cudaGetSymbolAddress((void**)&wdec,   g_wdec);
    cudaGetSymbolAddress((void**)&gi_dec, g_gi_dec);
    cudaGetSymbolAddress((void**)&gi_ctx, g_gi_ctx);
    cudaGetSymbolAddress((void**)&hA,     g_hA);
    cudaGetSymbolAddress((void**)&hB,     g_hB);
    cudaGetSymbolAddress((void**)&states, g_states);
    cudaGetSymbolAddress((void**)&WhE,    g_Wh_enc);
    cudaGetSymbolAddress((void**)&WlE,    g_Wl_enc);
    cudaGetSymbolAddress((void**)&WhD,    g_Wh_dec);
    cudaGetSymbolAddress((void**)&WlD,    g_Wl_dec);
    cudaGetSymbolAddress((void**)&hpH,    g_hp_h);
    cudaGetSymbolAddress((void**)&hpL,    g_hp_l);

    uint32_t* hpHp[2] = { hpH, hpH + BB * KW };
    uint32_t* hpLp[2] = { hpL, hpL + BB * KW };

    // ---- weight pre-split (amortized over 192 recurrence steps) ----
    pack_w<<<H3, KW>>>(enc_Whh, WhE, WlE);
    pack_w<<<H3, KW>>>(dec_Whh, WhD, WlD);

    // ---- encoder ----
    gather_enc<<<TE * BB, 128>>>(x, enc_emb, xe);
    sgemm_nt<<<dim3(H3 / 128, (TE * BB) / 128), 256>>>(
        xe, enc_Wih, enc_bih, gi_enc, TE * BB, H3, DE, DE, DE);
    set_h_packed<<<BB, KW>>>(hA, hpHp[0], hpLp[0], nullptr);
    for (int t = 0; t < TE; t++) {
        int pi = t & 1, po = pi ^ 1;
        float* hin  = pi ? hB : hA;
        float* hout = pi ? hA : hB;
        gru_step_bf16<<<64, 256>>>(gi_enc + (size_t)t * BB * H3, nullptr,
                                   WhE, WlE, enc_bhh,
                                   hin, hpHp[pi], hpLp[pi],
                                   hout, hpHp[po], hpLp[po], nullptr, 0);
    }
    // encoder final state: t=127 wrote hout=hA (pi=1), packed slot 0

    // ---- decoder precompute ----
    gather_dec<<<TD * BB, 128>>>(labels, bos, dec_emb, wdec);
    sgemm_nt<<<dim3(H3 / 128, (TD * BB) / 128), 256>>>(
        wdec, dec_Wih, dec_bih, gi_dec, TD * BB, H3, DE, DE, DIN);
    sgemm_nt<<<dim3(H3 / 128, 1), 256>>>(
        hA, dec_Wih + DE, nullptr, gi_ctx, BB, H3, DH, DH, DIN);
    set_h_packed<<<BB, KW>>>(hA, hpHp[0], hpLp[0], dec_init);

    // ---- decoder recurrence ----
    for (int t = 0; t < TD; t++) {
        int pi = t & 1, po = pi ^ 1;
        float* hin  = pi ? hB : hA;
        float* hout = pi ? hA : hB;
        gru_step_bf16<<<64, 256>>>(gi_dec + (size_t)t * BB * H3, gi_ctx,
                                   WhD, WlD, dec_bhh,
                                   hin, hpHp[pi], hpLp[pi],
                                   hout, hpHp[po], hpLp[po],
                                   states + (size_t)t * DH, TD * DH);
    }

    // ---- output projection (tf32 tensor cores): logits = states * lin_W^T + lin_b ----
    gemm_tf32_nt<<<dim3(VV / 128, (TD * BB) / 128), 256>>>(
        states, lin_W, lin_b, out, TD * BB, VV, DH);
}